// round 8
// baseline (speedup 1.0000x reference)
#include <cuda_runtime.h>
#include <cuda_bf16.h>
#include <cstdint>

// CTC forward negative log-likelihood (keras ctc_batch_cost semantics).
// B=128, T=1024, V=512, L=128, S=2L+1=257, blank=V-1.
//
// Round-7 design ("mailbox wavefront", log2 domain):
//  - 1 CTA per batch (grid=128), 128 threads (4 warps), checkerboard: thread k
//    owns states 2k (blank) and 2k+1 (label); alpha in registers; intra-warp
//    neighbor via software-pipelined __shfl_up; state 256 on lane31/warp3.
//  - NO per-step __syncthreads. Cross-warp sync via 64-bit shared mailboxes
//    {tag,value} with st.release.cta / ld.acquire.cta, 4-slot ring per warp.
//    Gates for step t (all reference step t-1 completions -> layered DAG,
//    deadlock-free):
//      warp0: C3>=t          (rows ready)
//      warp1: C0>=t, C3>=t   (halo + rows)
//      warp2: C1>=t, C3>=t
//      warp3: C0,C1,C2>=t    (halo from C2; all>=t makes row-slot overwrite safe)
//  - Probability rows staged by WARP 3 only (trailing warp): 4 x cp.async.cg
//    16B per lane per step into a 16-deep ring; wait_group<D-2> then publish
//    (publish = rows<=t+1 complete). Publishes are AFTER the row prefetch LDS
//    so release ordering covers prefetches of laggards.
//  - pO/pB prefetched one step ahead; log2-domain recursion (ex2/lg2.approx).

#define NEGV (-1e30f)
#define EPSV (1e-7f)
#define LN2F (0.6931471805599453f)

constexpr int Bc = 128;
constexpr int Tc = 1024;
constexpr int Vc = 512;
constexpr int Lc = 128;
constexpr int Sc = 257;     // 2L+1
constexpr int D  = 16;      // row ring stages (32KB)
constexpr int NT = 128;     // 4 warps
constexpr int Hm = 4;       // mailbox ring slots

__device__ __forceinline__ float ex2f(float x) {
    float r; asm("ex2.approx.f32 %0, %1;" : "=f"(r) : "f"(x)); return r;
}
__device__ __forceinline__ float lg2f(float x) {
    float r; asm("lg2.approx.f32 %0, %1;" : "=f"(r) : "f"(x)); return r;
}
__device__ __forceinline__ void cp_async16(uint32_t saddr, const void* gptr) {
    asm volatile("cp.async.cg.shared.global [%0], [%1], 16;" :: "r"(saddr), "l"(gptr));
}
__device__ __forceinline__ void cp_commit() {
    asm volatile("cp.async.commit_group;");
}
template<int N>
__device__ __forceinline__ void cp_wait() {
    asm volatile("cp.async.wait_group %0;" :: "n"(N));
}
// Poll mailbox until tag (hi 32) >= need; returns value (lo 32 as float).
__device__ __forceinline__ float poll_mail(uint32_t addr, unsigned need) {
    unsigned long long v;
    #pragma unroll 1
    do {
        asm volatile("ld.acquire.cta.shared.b64 %0, [%1];" : "=l"(v) : "r"(addr));
    } while ((unsigned)(v >> 32) < need);
    return __uint_as_float((unsigned)(v & 0xffffffffull));
}
__device__ __forceinline__ void push_mail(uint32_t addr, unsigned tag, float val) {
    unsigned long long v = ((unsigned long long)tag << 32)
                         | (unsigned long long)__float_as_uint(val);
    asm volatile("st.release.cta.shared.b64 [%0], %1;" :: "r"(addr), "l"(v));
}

__global__ __launch_bounds__(NT, 1)
void ctc_forward_kernel(const int*   __restrict__ labels,     // [B, L]
                        const int*   __restrict__ lab_len,    // [B, 1]
                        const float* __restrict__ Y,          // [B, T, V]
                        const int*   __restrict__ in_len,     // [B, 1]
                        float*       __restrict__ out)        // [B, 1]
{
    __shared__ __align__(16) float rows[D][Vc];                 // 32KB row ring
    __shared__ __align__(8)  unsigned long long mail[4][Hm];    // {tag,val}
    __shared__ int   lab_sh[Lc];
    __shared__ float alpha_fin[Sc + 3];

    const int b    = blockIdx.x;
    const int tid  = threadIdx.x;
    const int wid  = tid >> 5;
    const int lane = tid & 31;

    lab_sh[tid] = labels[b * Lc + tid];
    const int len = in_len[b];

    if (tid < 16) mail[tid >> 2][tid & 3] =
        (unsigned long long)__float_as_uint(NEGV);   // tag=0, val=NEGV

    const float* __restrict__ Yb = Y + (size_t)b * Tc * Vc;
    const uint32_t rows_sb = (uint32_t)__cvta_generic_to_shared(&rows[0][0]);
    const uint32_t mail_sb = (uint32_t)__cvta_generic_to_shared(&mail[0][0]);

    // ---- prologue: warp 3 stages rows 0..D-1 (one commit group per row) ----
    if (wid == 3) {
        #pragma unroll
        for (int j = 0; j < D; j++) {
            const int tr = (j < len) ? j : (len > 0 ? len - 1 : 0);
            const char* src = (const char*)(Yb + (size_t)tr * Vc);
            const uint32_t dst = rows_sb + (uint32_t)j * 2048u + (uint32_t)lane * 16u;
            #pragma unroll
            for (int c = 0; c < 4; c++)
                cp_async16(dst + c * 512u, src + c * 512 + lane * 16);
            cp_commit();
        }
        cp_wait<D - 2>();            // rows 0,1 complete
    }
    __syncthreads();                 // labels, mail init, rows 0,1 visible

    // ---- roles ----
    const int  k      = tid;                 // owns states 2k, 2k+1
    const int  blank  = Vc - 1;
    const int  cls    = lab_sh[k];
    const bool cskip  = (k > 0) && (cls != blank) && (cls != lab_sh[k - 1]);
    const bool isLast = (tid == NT - 1);     // also owns state 256

    float aE   = (k == 0) ? 0.0f : NEGV;     // log2 domain
    float aO   = NEGV;
    float a256 = NEGV;

    float pO = rows[0][cls];
    float pB = rows[0][blank];
    float nb = NEGV;                         // old_odd[k-1] (pipelined shfl)
    const uint32_t mb0 = mail_sb;
    const uint32_t mb1 = mail_sb + 32u;
    const uint32_t mb2 = mail_sb + 64u;
    const uint32_t mb3 = mail_sb + 96u;
    const uint32_t mbSelf = mail_sb + (uint32_t)wid * 32u;

    // ---- main recursion ----
    for (int t = 0; t < len; ++t) {
        const unsigned  need    = (unsigned)t;
        const uint32_t  slotoff = (uint32_t)((t + 3) & 3) * 8u;

        // gates (see header); value from mail[wid-1] is the halo
        float mval = NEGV;
        if (wid == 0) {
            (void)poll_mail(mb3 + slotoff, need);
        } else if (wid == 1) {
            mval = poll_mail(mb0 + slotoff, need);
            (void)poll_mail(mb3 + slotoff, need);
        } else if (wid == 2) {
            mval = poll_mail(mb1 + slotoff, need);
            (void)poll_mail(mb3 + slotoff, need);
        } else {
            (void)poll_mail(mb0 + slotoff, need);
            (void)poll_mail(mb1 + slotoff, need);
            mval = poll_mail(mb2 + slotoff, need);
        }

        const float nbv = (lane == 0) ? ((wid > 0) ? mval : NEGV) : nb;

        // odd/label state 2k+1: terms {aO, aE, cskip ? nbv : NEG}
        const float a2 = cskip ? nbv : NEGV;
        const float hi = fmaxf(aO, aE);
        const float lo = fminf(aO, aE);
        const float m  = fmaxf(hi, a2);
        const float x  = fminf(hi, a2);
        const float nO = m + lg2f((1.0f + ex2f(lo - m) + ex2f(x - m)) * (pO + EPSV));

        // even/blank state 2k: terms {aE, nbv}
        const float mE  = fmaxf(aE, nbv);
        const float loE = fminf(aE, nbv);
        const float nE  = mE + lg2f((1.0f + ex2f(loE - mE)) * (pB + EPSV));

        // state 256 (lane31/warp3): terms {a256, aO(state 255 = own)}
        if (isLast) {
            const float m2 = fmaxf(a256, aO);
            const float l2 = fminf(a256, aO);
            a256 = m2 + lg2f((1.0f + ex2f(l2 - m2)) * (pB + EPSV));
        }

        aE = nE; aO = nO;

        // prefetch p for step t+1 (row t+1 ready: C3 >= t -> rows <= t+1)
        const int st1 = (t + 1) & (D - 1);
        pO = rows[st1][cls];
        pB = rows[st1][blank];

        // warp 3: produce row t+D into slot t%D (safe: all C >= t), then drain
        if (wid == 3) {
            if (t + D < len) {
                const char* src = (const char*)(Yb + (size_t)(t + D) * Vc);
                const uint32_t dst = rows_sb + (uint32_t)(t & (D - 1)) * 2048u
                                   + (uint32_t)lane * 16u;
                #pragma unroll
                for (int c = 0; c < 4; c++)
                    cp_async16(dst + c * 512u, src + c * 512 + lane * 16);
                cp_commit();
                cp_wait<D - 2>();    // rows <= t+2 complete
            } else {
                cp_wait<0>();        // tail: drain everything
            }
            __syncwarp();            // all lanes' groups visible before publish
        }

        // publish completion of step t (AFTER prefetch -> release orders it)
        if (lane == 31)
            push_mail(mbSelf + (uint32_t)(t & 3) * 8u, (unsigned)(t + 1), nO);

        // pipeline the intra-warp neighbor for step t+1
        nb = __shfl_up_sync(0xffffffffu, nO, 1);
    }

    // ---- epilogue ----
    alpha_fin[2 * k]     = aE;
    alpha_fin[2 * k + 1] = aO;
    if (isLast) alpha_fin[256] = a256;
    __syncthreads();
    if (tid == 0) {
        const int   ll = lab_len[b];
        const float aL = alpha_fin[2 * ll];
        const float aP = alpha_fin[2 * ll - 1];
        const float mm = fmaxf(aL, aP);
        const float ql = fminf(aL, aP);
        out[b] = -LN2F * (mm + lg2f(1.0f + ex2f(ql - mm)));
    }
}

extern "C" void kernel_launch(void* const* d_in, const int* in_sizes, int n_in,
                              void* d_out, int out_size) {
    const int*   labels  = (const int*)d_in[0];   // true_labels [B, L]
    const int*   lab_len = (const int*)d_in[1];   // true_lengths [B, 1]
    const float* Y       = (const float*)d_in[2]; // predicted_labels [B, T, V]
    const int*   in_len  = (const int*)d_in[3];   // predicted_lengths [B, 1]
    float*       out     = (float*)d_out;         // [B, 1]

    ctc_forward_kernel<<<Bc, NT>>>(labels, lab_len, Y, in_len, out);
}

// round 9
// speedup vs baseline: 2.3152x; 2.3152x over previous
#include <cuda_runtime.h>
#include <cuda_bf16.h>
#include <cstdint>

// CTC forward negative log-likelihood (keras ctc_batch_cost semantics).
// B=128, T=1024, V=512, L=128, S=2L+1=257, blank=V-1.
//
// Round-8 design ("2 steps per barrier via ghost-zone redundancy"):
//  - 1 CTA per batch (grid=128), 288 threads (9 warps). Thread tid owns state
//    s = tid (tid <= 256). Per 2-step iteration it reads alpha_t[s-4..s] from
//    the shared double buffer (front-padded with 4 NEGV entries -> no bounds
//    branches), redundantly computes step-t updates for states s, s-1, s-2 in
//    registers, then the step-(t+1) update for s, and stores alpha_{t+2}[s].
//    => ONE __syncthreads per TWO time steps (barrier count halved vs R2).
//  - Uniform 3-term logaddexp2 update everywhere (dead terms = NEGV); no warp
//    divergence, conflict-free alpha LDS.
//  - Probability rows staged into an 8-deep shared ring via coalesced
//    cp.async.cg by tid<128 (2 rows per commit group). wait_group<2> before
//    the barrier guarantees the next iteration's 2 rows; overwrite of retired
//    slots is issued after the barrier.
//  - log2-domain recursion (raw ex2/lg2.approx), final scaled by ln2.

#define NEGV (-1e30f)
#define EPSV (1e-7f)
#define LN2F (0.6931471805599453f)

constexpr int Bc = 128;
constexpr int Tc = 1024;
constexpr int Vc = 512;
constexpr int Lc = 128;
constexpr int Sc = 257;     // 2L+1
constexpr int D  = 8;       // ring stages (16KB)
constexpr int NT = 288;     // 9 warps

__device__ __forceinline__ float ex2f(float x) {
    float r; asm("ex2.approx.f32 %0, %1;" : "=f"(r) : "f"(x)); return r;
}
__device__ __forceinline__ float lg2f(float x) {
    float r; asm("lg2.approx.f32 %0, %1;" : "=f"(r) : "f"(x)); return r;
}
__device__ __forceinline__ void cp_async16(uint32_t saddr, const void* gptr) {
    asm volatile("cp.async.cg.shared.global [%0], [%1], 16;" :: "r"(saddr), "l"(gptr));
}
__device__ __forceinline__ void cp_commit() {
    asm volatile("cp.async.commit_group;");
}
template<int N>
__device__ __forceinline__ void cp_wait() {
    asm volatile("cp.async.wait_group %0;" :: "n"(N));
}

// logaddexp2(a, b, c) + lg2(p):  m + lg2((1 + 2^(lo-m) + 2^(x-m)) * p)
__device__ __forceinline__ float up3(float a, float b, float c, float p) {
    const float hi = fmaxf(a, b);
    const float lo = fminf(a, b);
    const float m  = fmaxf(hi, c);
    const float x  = fminf(hi, c);
    return m + lg2f((1.0f + ex2f(lo - m) + ex2f(x - m)) * p);
}

__global__ __launch_bounds__(NT, 1)
void ctc_forward_kernel(const int*   __restrict__ labels,     // [B, L]
                        const int*   __restrict__ lab_len,    // [B, 1]
                        const float* __restrict__ Y,          // [B, T, V]
                        const int*   __restrict__ in_len,     // [B, 1]
                        float*       __restrict__ out)        // [B, 1]
{
    __shared__ __align__(16) float rows[D][Vc];   // staged probability rows
    __shared__ float As[2][Sc + 8];               // alpha, 4 front-pad + 3 tail
    __shared__ int   lab_sh[Lc];

    const int b   = blockIdx.x;
    const int tid = threadIdx.x;

    if (tid < Lc) lab_sh[tid] = labels[b * Lc + tid];
    const int len = in_len[b];

    const bool active = (tid <= 256);
    const int  s      = tid;

    // init: front pads (both buffers) + alpha0
    if (tid < 4) { As[0][tid] = NEGV; As[1][tid] = NEGV; }
    if (active) As[0][4 + s] = (s == 0) ? 0.0f : NEGV;   // log2 domain

    const float* __restrict__ Yb = Y + (size_t)b * Tc * Vc;
    const bool producer = (tid < 128);
    const uint32_t rows_sb = (uint32_t)__cvta_generic_to_shared(&rows[0][0]);

    // ---- prologue: stage rows 0..D-1 as D/2 groups of 2 rows ----
    if (producer) {
        #pragma unroll
        for (int g = 0; g < D / 2; g++) {
            #pragma unroll
            for (int r = 0; r < 2; r++) {
                const int j  = 2 * g + r;
                const int tr = (j < len) ? j : (len > 0 ? len - 1 : 0);
                cp_async16(rows_sb + (uint32_t)j * 2048u + (uint32_t)tid * 16u,
                           Yb + (size_t)tr * Vc + tid * 4);
            }
            cp_commit();
        }
        cp_wait<2>();                 // rows 0..3 complete
    }
    __syncthreads();                  // labels, alpha0, rows visible

    // ---- per-thread constants (setup-only divergence) ----
    const int blank = Vc - 1;
    int  cls_s = blank, cls_m1 = blank, cls_m2 = blank;
    bool cs_s = false, cs_m1 = false, cs_m2 = false;
    if (active) {
        if (s & 1) {                              // odd: s = 2l+1
            const int l = (s - 1) >> 1;
            cls_s  = lab_sh[l];
            cls_m2 = lab_sh[(l >= 1) ? (l - 1) : 0];
            cs_s   = (l >= 1) && (cls_s != cls_m2) && (cls_s != blank);
            cs_m2  = (l >= 2) && (lab_sh[l - 1] != lab_sh[l - 2]) && (lab_sh[l - 1] != blank);
        } else {                                  // even: s = 2l
            const int l = s >> 1;
            cls_m1 = lab_sh[(l >= 1) ? (l - 1) : 0];
            cs_m1  = (l >= 2) && (lab_sh[l - 1] != lab_sh[l - 2]) && (lab_sh[l - 1] != blank);
        }
    }

    // ---- main recursion: 2 steps per barrier ----
    int rd = 0;
    for (int t = 0; t < len; t += 2) {
        const int sl0 = t & (D - 1);
        const int sl1 = (t + 1) & (D - 1);

        if (active) {
            // alpha_t[s-4..s]  (front pad absorbs s<4)
            const float* Ar = &As[rd][s];         // Ar[j] = alpha_t[s-4+j]
            const float A0 = Ar[4];               // alpha[s]
            const float A1 = Ar[3];               // alpha[s-1]
            const float A2 = Ar[2];
            const float A3 = Ar[1];
            const float A4 = Ar[0];

            const float p_s  = rows[sl0][cls_s]  + EPSV;
            const float p_m1 = rows[sl0][cls_m1] + EPSV;
            const float p_m2 = rows[sl0][cls_m2] + EPSV;
            const float q_s  = rows[sl1][cls_s]  + EPSV;

            // step t (ghost zone)
            const float b0 = up3(A0, A1, cs_s  ? A2 : NEGV, p_s);
            const float b1 = up3(A1, A2, cs_m1 ? A3 : NEGV, p_m1);
            const float b2 = up3(A2, A3, cs_m2 ? A4 : NEGV, p_m2);
            // step t+1 (own state only)
            const float n = (t + 1 < len) ? up3(b0, b1, cs_s ? b2 : NEGV, q_s)
                                          : b0;
            As[rd ^ 1][4 + s] = n;
        }

        if (producer) cp_wait<2>();   // next iteration's rows complete
        __syncthreads();              // publish alpha_{t+2} and staged rows
        if (producer && (t + D) < len) {
            #pragma unroll
            for (int r = 0; r < 2; r++) {
                const int j  = t + D + r;
                const int tr = (j < len) ? j : (len - 1);
                cp_async16(rows_sb + (uint32_t)(j & (D - 1)) * 2048u + (uint32_t)tid * 16u,
                           Yb + (size_t)tr * Vc + tid * 4);
            }
            cp_commit();
        }
        rd ^= 1;
    }

    // ---- final: loss = -ln2 * logaddexp2(alpha[2*lab], alpha[2*lab-1]) ----
    if (tid == 0) {
        const int   ll = lab_len[b];
        const float aL = As[rd][4 + 2 * ll];
        const float aP = As[rd][4 + 2 * ll - 1];
        const float mm = fmaxf(aL, aP);
        const float ql = fminf(aL, aP);
        out[b] = -LN2F * (mm + lg2f(1.0f + ex2f(ql - mm)));
    }
}

extern "C" void kernel_launch(void* const* d_in, const int* in_sizes, int n_in,
                              void* d_out, int out_size) {
    const int*   labels  = (const int*)d_in[0];   // true_labels [B, L]
    const int*   lab_len = (const int*)d_in[1];   // true_lengths [B, 1]
    const float* Y       = (const float*)d_in[2]; // predicted_labels [B, T, V]
    const int*   in_len  = (const int*)d_in[3];   // predicted_lengths [B, 1]
    float*       out     = (float*)d_out;         // [B, 1]

    ctc_forward_kernel<<<Bc, NT>>>(labels, lab_len, Y, in_len, out);
}